// round 1
// baseline (speedup 1.0000x reference)
#include <cuda_runtime.h>

// Problem constants (fixed shapes from the reference)
#define B_DIM   4
#define S_DIM   4096
#define NTOK    (B_DIM * S_DIM)      // 16384 tokens
#define D_DIM   1024
#define OUT_DIM 4096
#define NMOD    2

// Scratch (allocation-free rule: __device__ globals)
__device__ int g_counts[NMOD];
__device__ int g_idx[NMOD * NTOK];

// ---------------------------------------------------------------------------
// Pass 1: reset counters
__global__ void reset_counts_kernel() {
    if (threadIdx.x < NMOD) g_counts[threadIdx.x] = 0;
}

// Pass 2: build per-expert token lists (order nondeterministic, output isn't:
// each token's result is independent of its position in the list)
__global__ void build_lists_kernel(const int* __restrict__ type_ids) {
    int i = blockIdx.x * blockDim.x + threadIdx.x;
    if (i < NTOK) {
        int t = type_ids[i];
        int p = atomicAdd(&g_counts[t], 1);
        g_idx[t * NTOK + p] = i;
    }
}

// ---------------------------------------------------------------------------
// Pass 3: gathered SGEMM. Per expert e: rows = its token list, cols = OUT.
// Tile 128x128, BK=8, 256 threads, 8x8 per-thread micro-tile, double-buffered.
// Epilogue: write (acc + bias) to plane e, write 0 to plane (1-e) at the same
// (token, col) — together the two experts' blocks cover every output element.
#define BM 128
#define BN 128
#define BK 8
#define TM 8
#define TN 8

__global__ __launch_bounds__(256, 2)
void moe_gemm_kernel(const float* __restrict__ X,
                     const float* __restrict__ W0, const float* __restrict__ b0,
                     const float* __restrict__ W1, const float* __restrict__ b1,
                     float* __restrict__ out)
{
    const int e = blockIdx.z;
    const int cnt = g_counts[e];
    const int rowBase = blockIdx.y * BM;
    if (rowBase >= cnt) return;

    const float* __restrict__ W    = e ? W1 : W0;
    const float* __restrict__ bias = e ? b1 : b0;
    const int*   __restrict__ idx  = g_idx + e * NTOK;

    __shared__ float As[2][BK][BM];
    __shared__ float Bs[2][BK][BN];
    __shared__ int   tok[BM];

    const int tid = threadIdx.x;

    // Stage the gathered token ids for this row tile
    if (tid < BM) {
        int r = rowBase + tid;
        tok[tid] = (r < cnt) ? idx[r] : -1;
    }
    __syncthreads();

    const int colBase = blockIdx.x * BN;

    // A tile loader: 128 rows x 8 k-cols; one float4 per thread
    const int aRow = tid >> 1;            // 0..127
    const int aCol = (tid & 1) * 4;       // 0 or 4
    const int aTok = tok[aRow];
    const float* aPtr = (aTok >= 0) ? (X + (size_t)aTok * D_DIM + aCol) : nullptr;

    // B tile loader: 8 k-rows x 128 cols; one float4 per thread
    const int bRow = tid >> 5;            // 0..7
    const int bCol = (tid & 31) * 4;      // 0..124
    const float* bPtr = W + (size_t)bRow * OUT_DIM + colBase + bCol;

    const int tx = tid & 15;              // col group  (tx*8 .. tx*8+7)
    const int ty = tid >> 4;              // row group  (ty*8 .. ty*8+7)

    float acc[TM][TN];
    #pragma unroll
    for (int i = 0; i < TM; i++)
        #pragma unroll
        for (int j = 0; j < TN; j++) acc[i][j] = 0.0f;

    // Prologue: load k-tile 0
    float4 a4 = aPtr ? *(const float4*)aPtr : make_float4(0.f, 0.f, 0.f, 0.f);
    float4 b4 = *(const float4*)bPtr;
    As[0][aCol + 0][aRow] = a4.x;
    As[0][aCol + 1][aRow] = a4.y;
    As[0][aCol + 2][aRow] = a4.z;
    As[0][aCol + 3][aRow] = a4.w;
    *(float4*)&Bs[0][bRow][bCol] = b4;
    __syncthreads();

    int buf = 0;
    for (int k0 = BK; k0 <= D_DIM; k0 += BK) {
        const bool more = (k0 < D_DIM);
        float4 a4n, b4n;
        if (more) {
            a4n = aPtr ? *(const float4*)(aPtr + k0) : make_float4(0.f, 0.f, 0.f, 0.f);
            b4n = *(const float4*)(bPtr + (size_t)k0 * OUT_DIM);
        }

        #pragma unroll
        for (int k = 0; k < BK; k++) {
            float af[TM], bf[TN];
            #pragma unroll
            for (int i = 0; i < TM; i++) af[i] = As[buf][k][ty * TM + i];
            #pragma unroll
            for (int j = 0; j < TN; j++) bf[j] = Bs[buf][k][tx * TN + j];
            #pragma unroll
            for (int i = 0; i < TM; i++)
                #pragma unroll
                for (int j = 0; j < TN; j++)
                    acc[i][j] = fmaf(af[i], bf[j], acc[i][j]);
        }

        if (more) {
            const int nb = buf ^ 1;
            // nb's previous readers all synced at the end of the prior iter;
            // current readers read 'buf' only -> safe single-sync double buffer
            As[nb][aCol + 0][aRow] = a4n.x;
            As[nb][aCol + 1][aRow] = a4n.y;
            As[nb][aCol + 2][aRow] = a4n.z;
            As[nb][aCol + 3][aRow] = a4n.w;
            *(float4*)&Bs[nb][bRow][bCol] = b4n;
            __syncthreads();
            buf = nb;
        }
    }

    // Epilogue
    float bv[TN];
    #pragma unroll
    for (int j = 0; j < TN; j++) bv[j] = bias[colBase + tx * TN + j];

    const size_t planeMine  = (size_t)e * NTOK * OUT_DIM;
    const size_t planeOther = (size_t)(1 - e) * NTOK * OUT_DIM;
    const int colOff = colBase + tx * TN;

    #pragma unroll
    for (int i = 0; i < TM; i++) {
        const int r = ty * TM + i;
        const int t = tok[r];
        if (t < 0) continue;
        float* po = out + planeMine  + (size_t)t * OUT_DIM + colOff;
        float* pz = out + planeOther + (size_t)t * OUT_DIM + colOff;
        float4 v0 = make_float4(acc[i][0] + bv[0], acc[i][1] + bv[1],
                                acc[i][2] + bv[2], acc[i][3] + bv[3]);
        float4 v1 = make_float4(acc[i][4] + bv[4], acc[i][5] + bv[5],
                                acc[i][6] + bv[6], acc[i][7] + bv[7]);
        const float4 z = make_float4(0.f, 0.f, 0.f, 0.f);
        ((float4*)po)[0] = v0;
        ((float4*)po)[1] = v1;
        ((float4*)pz)[0] = z;
        ((float4*)pz)[1] = z;
    }
}

// ---------------------------------------------------------------------------
extern "C" void kernel_launch(void* const* d_in, const int* in_sizes, int n_in,
                              void* d_out, int out_size)
{
    const float* X   = (const float*)d_in[0];  // hidden_states [B,S,D]
    const int*   tid = (const int*)  d_in[1];  // type_ids      [B,S]
    const float* W0  = (const float*)d_in[2];  // [D,OUT]
    const float* b0  = (const float*)d_in[3];  // [OUT]
    const float* W1  = (const float*)d_in[4];  // [D,OUT]
    const float* b1  = (const float*)d_in[5];  // [OUT]
    float* out = (float*)d_out;                // [M,B,S,OUT]

    reset_counts_kernel<<<1, 32>>>();
    build_lists_kernel<<<(NTOK + 255) / 256, 256>>>(tid);

    dim3 grid(OUT_DIM / BN, NTOK / BM, NMOD);  // 32 x 128 x 2
    moe_gemm_kernel<<<grid, 256>>>(X, W0, b0, W1, b1, out);
}

// round 3
// speedup vs baseline: 3.4635x; 3.4635x over previous
#include <cuda_runtime.h>
#include <cstdint>

// ---------------- problem constants ----------------
#define NTOK    16384
#define D_DIM   1024
#define OUT_DIM 4096
#define NMOD    2
#define PLANE   ((size_t)NTOK * OUT_DIM)

#define BM 128
#define BN 128
#define BK 16
#define KITERS (D_DIM / BK)       // 64
#define NSTAGE 4
#define THREADS 256

// smem geometry (floats)
#define APAD 20                    // row stride for As[m][APAD]
#define BPAD 136                   // row stride for Bs[k][BPAD]
#define ASZ  (BM * APAD * 4)       // 10240 B
#define BSZ  (BK * BPAD * 4)       // 8704 B
#define STAGE (ASZ + BSZ)          // 18944 B
#define TOK_OFF  (NSTAGE * STAGE)          // 75776
#define BIAS_OFF (TOK_OFF + BM * 4)
#define SMEM_REQ (BIAS_OFF + BN * 4 + 256)

// ---------------- scratch (device globals; allocation-free rule) ----------------
__device__ int   g_counts[NMOD];
__device__ int   g_idx[NMOD * NTOK];
__device__ float g_Xg[(size_t)NMOD * NTOK * D_DIM];       // compacted + tf32-rounded X
__device__ float g_Wr[NMOD][(size_t)D_DIM * OUT_DIM];     // tf32-rounded W

// ---------------- helpers ----------------
__device__ __forceinline__ uint32_t smem_u32(const void* p) {
    uint32_t a;
    asm("{ .reg .u64 t; cvta.to.shared.u64 t, %1; cvt.u32.u64 %0, t; }" : "=r"(a) : "l"(p));
    return a;
}
__device__ __forceinline__ float rn_tf32(float x) {
    uint32_t r;
    asm("cvt.rna.tf32.f32 %0, %1;" : "=r"(r) : "f"(x));
    return __uint_as_float(r);
}
__device__ __forceinline__ void cp16(uint32_t dst, const void* src) {
    asm volatile("cp.async.cg.shared.global [%0], [%1], 16;" :: "r"(dst), "l"(src));
}
#define CP_COMMIT() asm volatile("cp.async.commit_group;" ::: "memory")
#define CP_WAIT2()  asm volatile("cp.async.wait_group 2;" ::: "memory")

__device__ __forceinline__ void mma_tf32(float* d, const uint32_t* a, const uint32_t* b) {
    asm volatile(
        "mma.sync.aligned.m16n8k8.row.col.f32.tf32.tf32.f32 "
        "{%0,%1,%2,%3}, {%4,%5,%6,%7}, {%8,%9}, {%0,%1,%2,%3};"
        : "+f"(d[0]), "+f"(d[1]), "+f"(d[2]), "+f"(d[3])
        : "r"(a[0]), "r"(a[1]), "r"(a[2]), "r"(a[3]), "r"(b[0]), "r"(b[1]));
}

// ---------------- pass 1/2: routing ----------------
__global__ void reset_counts_kernel() {
    if (threadIdx.x < NMOD) g_counts[threadIdx.x] = 0;
}
__global__ void build_lists_kernel(const int* __restrict__ type_ids) {
    int i = blockIdx.x * blockDim.x + threadIdx.x;
    if (i < NTOK) {
        int t = type_ids[i];
        int p = atomicAdd(&g_counts[t], 1);
        g_idx[t * NTOK + p] = i;
    }
}

// ---------------- pass 3: round W -> g_Wr ----------------
__global__ void round_w_kernel(const float* __restrict__ W0, const float* __restrict__ W1) {
    size_t i = (size_t)blockIdx.x * blockDim.x + threadIdx.x;   // over float4 of both Ws
    const size_t nf4 = (size_t)D_DIM * OUT_DIM / 4;             // 1M per expert
    const float4* src = (i < nf4) ? ((const float4*)W0 + i) : ((const float4*)W1 + (i - nf4));
    float* dst = (i < nf4) ? (&g_Wr[0][0] + i * 4) : (&g_Wr[1][0] + (i - nf4) * 4);
    float4 v = *src;
    dst[0] = rn_tf32(v.x); dst[1] = rn_tf32(v.y);
    dst[2] = rn_tf32(v.z); dst[3] = rn_tf32(v.w);
}

// ---------------- pass 4: gather + round X -> g_Xg (dense per-expert rows) ----------------
__global__ void gather_x_kernel(const float* __restrict__ X) {
    // 4 rows per block of 256 threads; 64 threads per row, 4 float4 each
    int p = blockIdx.x * 4 + (threadIdx.x >> 6);        // position over [NMOD*NTOK)
    int e = p >> 14;                                    // /NTOK
    int r = p & (NTOK - 1);
    if (r >= g_counts[e]) return;
    int tok = g_idx[e * NTOK + r];
    const float4* src = (const float4*)(X + (size_t)tok * D_DIM);
    float4* dst = (float4*)(g_Xg + ((size_t)e * NTOK + r) * D_DIM);
    int l = threadIdx.x & 63;
    #pragma unroll
    for (int q = 0; q < 4; q++) {
        float4 v = src[l + q * 64];
        v.x = rn_tf32(v.x); v.y = rn_tf32(v.y);
        v.z = rn_tf32(v.z); v.w = rn_tf32(v.w);
        dst[l + q * 64] = v;
    }
}

// ---------------- pass 5: tf32 mma.sync GEMM ----------------
__global__ __launch_bounds__(THREADS, 2)
void moe_gemm_mma(const float* __restrict__ b0v, const float* __restrict__ b1v,
                  float* __restrict__ out)
{
    const int e = blockIdx.z;
    const int cnt = g_counts[e];
    const int rowBase = blockIdx.y * BM;
    if (rowBase >= cnt) return;
    const int colBase = blockIdx.x * BN;

    extern __shared__ char sm[];
    const uint32_t smb = smem_u32(sm);

    const int tid = threadIdx.x;
    const int wid = tid >> 5;
    const int lane = tid & 31;
    const int g = lane >> 2;        // group 0..7
    const int c = lane & 3;         // thread-in-group 0..3
    const int wr = wid & 1;         // warp row (2 x 64)
    const int wc = wid >> 1;        // warp col (4 x 32)

    int*   tokS  = (int*)(sm + TOK_OFF);
    float* biasS = (float*)(sm + BIAS_OFF);
    const float* bias = e ? b1v : b0v;
    if (tid < BM) {
        int r = rowBase + tid;
        tokS[tid] = (r < cnt) ? g_idx[e * NTOK + r] : -1;
        biasS[tid] = bias[colBase + tid];
    }

    // per-thread load slots
    const float* Xbase = g_Xg + ((size_t)e * NTOK + rowBase) * D_DIM;
    const float* Wbase = &g_Wr[e][0] + colBase;

    // A: 512 float4 / tile; idx = q*256+tid; m = idx>>2, kc = idx&3
    const int am[2]  = { (0 * THREADS + tid) >> 2, (1 * THREADS + tid) >> 2 };
    const int akc[2] = { (0 * THREADS + tid) & 3,  (1 * THREADS + tid) & 3 };
    // B: idx = q*256+tid; k = idx>>5, n4 = idx&31
    const int bk[2]  = { (0 * THREADS + tid) >> 5, (1 * THREADS + tid) >> 5 };
    const int bn4[2] = { (0 * THREADS + tid) & 31, (1 * THREADS + tid) & 31 };

    uint32_t adst[2], bdst[2];
    #pragma unroll
    for (int q = 0; q < 2; q++) {
        adst[q] = smb + (uint32_t)(am[q] * APAD + akc[q] * 4) * 4;
        bdst[q] = smb + ASZ + (uint32_t)(bk[q] * BPAD + bn4[q] * 4) * 4;
    }

    // prologue: stages 0..2 = k-tiles 0..2
    #pragma unroll
    for (int t = 0; t < NSTAGE - 1; t++) {
        #pragma unroll
        for (int q = 0; q < 2; q++) {
            cp16(adst[q] + t * STAGE, Xbase + (size_t)am[q] * D_DIM + t * BK + akc[q] * 4);
            cp16(bdst[q] + t * STAGE, Wbase + (size_t)(t * BK + bk[q]) * OUT_DIM + bn4[q] * 4);
        }
        CP_COMMIT();
    }

    float acc[4][4][4];
    #pragma unroll
    for (int mt = 0; mt < 4; mt++)
        #pragma unroll
        for (int nt = 0; nt < 4; nt++)
            #pragma unroll
            for (int r = 0; r < 4; r++) acc[mt][nt][r] = 0.f;

    for (int i = 0; i < KITERS; i++) {
        CP_WAIT2();
        __syncthreads();

        const int t = i + NSTAGE - 1;
        if (t < KITERS) {
            const int fs = t & (NSTAGE - 1);
            #pragma unroll
            for (int q = 0; q < 2; q++) {
                cp16(adst[q] + fs * STAGE, Xbase + (size_t)am[q] * D_DIM + t * BK + akc[q] * 4);
                cp16(bdst[q] + fs * STAGE, Wbase + (size_t)(t * BK + bk[q]) * OUT_DIM + bn4[q] * 4);
            }
            CP_COMMIT();
        }

        const int slot = i & (NSTAGE - 1);
        const float* As = (const float*)(sm + slot * STAGE);
        const float* Bs = (const float*)(sm + slot * STAGE + ASZ);

        #pragma unroll
        for (int ks = 0; ks < 2; ks++) {
            uint32_t af[4][4], bf[4][2];
            #pragma unroll
            for (int mt = 0; mt < 4; mt++) {
                const int m = wr * 64 + mt * 16;
                af[mt][0] = __float_as_uint(As[(m + g)     * APAD + ks * 8 + c]);
                af[mt][1] = __float_as_uint(As[(m + g + 8) * APAD + ks * 8 + c]);
                af[mt][2] = __float_as_uint(As[(m + g)     * APAD + ks * 8 + c + 4]);
                af[mt][3] = __float_as_uint(As[(m + g + 8) * APAD + ks * 8 + c + 4]);
            }
            #pragma unroll
            for (int nt = 0; nt < 4; nt++) {
                const int n = wc * 32 + nt * 8 + g;
                bf[nt][0] = __float_as_uint(Bs[(ks * 8 + c)     * BPAD + n]);
                bf[nt][1] = __float_as_uint(Bs[(ks * 8 + c + 4) * BPAD + n]);
            }
            #pragma unroll
            for (int mt = 0; mt < 4; mt++)
                #pragma unroll
                for (int nt = 0; nt < 4; nt++)
                    mma_tf32(acc[mt][nt], af[mt], bf[nt]);
        }
        __syncthreads();
    }

    // ---- epilogue ----
    const size_t pMine  = (size_t)e * PLANE;
    const size_t pOther = (size_t)(1 - e) * PLANE;

    #pragma unroll
    for (int mt = 0; mt < 4; mt++) {
        #pragma unroll
        for (int half = 0; half < 2; half++) {
            const int r = wr * 64 + mt * 16 + g + half * 8;
            const int tok = tokS[r];
            if (tok < 0) continue;
            #pragma unroll
            for (int nt = 0; nt < 4; nt++) {
                const int coll = wc * 32 + nt * 8 + 2 * c;   // block-local col
                const float v0 = acc[mt][nt][half * 2 + 0] + biasS[coll];
                const float v1 = acc[mt][nt][half * 2 + 1] + biasS[coll + 1];
                float2* po = (float2*)(out + pMine  + (size_t)tok * OUT_DIM + colBase + coll);
                float2* pz = (float2*)(out + pOther + (size_t)tok * OUT_DIM + colBase + coll);
                *po = make_float2(v0, v1);
                *pz = make_float2(0.f, 0.f);
            }
        }
    }
}

// ---------------- launch ----------------
extern "C" void kernel_launch(void* const* d_in, const int* in_sizes, int n_in,
                              void* d_out, int out_size)
{
    const float* X   = (const float*)d_in[0];
    const int*   tid = (const int*)  d_in[1];
    const float* W0  = (const float*)d_in[2];
    const float* b0  = (const float*)d_in[3];
    const float* W1  = (const float*)d_in[4];
    const float* b1  = (const float*)d_in[5];
    float* out = (float*)d_out;

    cudaFuncSetAttribute(moe_gemm_mma, cudaFuncAttributeMaxDynamicSharedMemorySize, SMEM_REQ);

    reset_counts_kernel<<<1, 32>>>();
    build_lists_kernel<<<(NTOK + 255) / 256, 256>>>(tid);
    round_w_kernel<<<(2 * D_DIM * OUT_DIM / 4 + 255) / 256, 256>>>(W0, W1);
    gather_x_kernel<<<(NMOD * NTOK) / 4, 256>>>(X);

    dim3 grid(OUT_DIM / BN, NTOK / BM, NMOD);     // 32 x 128 x 2
    moe_gemm_mma<<<grid, THREADS, SMEM_REQ>>>(b0, b1, out);
}

// round 4
// speedup vs baseline: 3.5989x; 1.0391x over previous
#include <cuda_runtime.h>
#include <cstdint>

// ---------------- problem constants ----------------
#define NTOK    16384
#define D_DIM   1024
#define OUT_DIM 4096
#define NMOD    2
#define PLANE   ((size_t)NTOK * OUT_DIM)

#define BM 128
#define BN 128
#define BK 16
#define KITERS (D_DIM / BK)       // 64
#define NSTAGE 4
#define THREADS 128               // 4 warps, 64x64 warp tile

// smem geometry (floats)
#define APAD 20
#define BPAD 136
#define ASZ  (BM * APAD * 4)      // 10240 B
#define BSZ  (BK * BPAD * 4)      // 8704 B
#define STAGE (ASZ + BSZ)         // 18944 B
#define TOK_OFF  (NSTAGE * STAGE)
#define BIAS_OFF (TOK_OFF + BM * 4)
#define SMEM_REQ (BIAS_OFF + BN * 4 + 256)

// ---------------- scratch ----------------
__device__ int   g_counts[NMOD];
__device__ int   g_idx[NMOD * NTOK];
__device__ float g_Xg[(size_t)NMOD * NTOK * D_DIM];
__device__ float g_Wr[NMOD][(size_t)D_DIM * OUT_DIM];

// ---------------- helpers ----------------
__device__ __forceinline__ uint32_t smem_u32(const void* p) {
    uint32_t a;
    asm("{ .reg .u64 t; cvta.to.shared.u64 t, %1; cvt.u32.u64 %0, t; }" : "=r"(a) : "l"(p));
    return a;
}
__device__ __forceinline__ float rn_tf32(float x) {
    uint32_t r;
    asm("cvt.rna.tf32.f32 %0, %1;" : "=r"(r) : "f"(x));
    return __uint_as_float(r);
}
__device__ __forceinline__ void cp16(uint32_t dst, const void* src) {
    asm volatile("cp.async.cg.shared.global [%0], [%1], 16;" :: "r"(dst), "l"(src));
}
#define CP_COMMIT() asm volatile("cp.async.commit_group;" ::: "memory")
#define CP_WAIT2()  asm volatile("cp.async.wait_group 2;" ::: "memory")

__device__ __forceinline__ void mma_tf32(float* d, const uint32_t* a, const uint32_t* b) {
    asm volatile(
        "mma.sync.aligned.m16n8k8.row.col.f32.tf32.tf32.f32 "
        "{%0,%1,%2,%3}, {%4,%5,%6,%7}, {%8,%9}, {%0,%1,%2,%3};"
        : "+f"(d[0]), "+f"(d[1]), "+f"(d[2]), "+f"(d[3])
        : "r"(a[0]), "r"(a[1]), "r"(a[2]), "r"(a[3]), "r"(b[0]), "r"(b[1]));
}

// ---------------- routing ----------------
__global__ void reset_counts_kernel() {
    if (threadIdx.x < NMOD) g_counts[threadIdx.x] = 0;
}
__global__ void build_lists_kernel(const int* __restrict__ type_ids) {
    int i = blockIdx.x * blockDim.x + threadIdx.x;
    if (i < NTOK) {
        int t = type_ids[i];
        int p = atomicAdd(&g_counts[t], 1);
        g_idx[t * NTOK + p] = i;
    }
}

// ---------------- round W ----------------
__global__ void round_w_kernel(const float* __restrict__ W0, const float* __restrict__ W1) {
    size_t i = (size_t)blockIdx.x * blockDim.x + threadIdx.x;
    const size_t nf4 = (size_t)D_DIM * OUT_DIM / 4;
    const float4* src = (i < nf4) ? ((const float4*)W0 + i) : ((const float4*)W1 + (i - nf4));
    float* dst = (i < nf4) ? (&g_Wr[0][0] + i * 4) : (&g_Wr[1][0] + (i - nf4) * 4);
    float4 v = *src;
    dst[0] = rn_tf32(v.x); dst[1] = rn_tf32(v.y);
    dst[2] = rn_tf32(v.z); dst[3] = rn_tf32(v.w);
}

// ---------------- gather + round X ----------------
__global__ void gather_x_kernel(const float* __restrict__ X) {
    int p = blockIdx.x * 4 + (threadIdx.x >> 6);
    int e = p >> 14;
    int r = p & (NTOK - 1);
    if (r >= g_counts[e]) return;
    int tok = g_idx[e * NTOK + r];
    const float4* src = (const float4*)(X + (size_t)tok * D_DIM);
    float4* dst = (float4*)(g_Xg + ((size_t)e * NTOK + r) * D_DIM);
    int l = threadIdx.x & 63;
    #pragma unroll
    for (int q = 0; q < 4; q++) {
        float4 v = src[l + q * 64];
        v.x = rn_tf32(v.x); v.y = rn_tf32(v.y);
        v.z = rn_tf32(v.z); v.w = rn_tf32(v.w);
        dst[l + q * 64] = v;
    }
}

// ---------------- tf32 mma.sync GEMM, 64x64 warp tiles ----------------
__global__ __launch_bounds__(THREADS, 2)
void moe_gemm_mma(const float* __restrict__ b0v, const float* __restrict__ b1v,
                  float* __restrict__ out)
{
    const int e = blockIdx.z;
    const int cnt = g_counts[e];
    const int rowBase = blockIdx.y * BM;
    if (rowBase >= cnt) return;
    const int colBase = blockIdx.x * BN;

    extern __shared__ char sm[];
    const uint32_t smb = smem_u32(sm);

    const int tid = threadIdx.x;
    const int wid = tid >> 5;
    const int lane = tid & 31;
    const int g = lane >> 2;
    const int c = lane & 3;
    const int wr = wid & 1;         // 2 warp rows x 64
    const int wc = wid >> 1;        // 2 warp cols x 64

    int*   tokS  = (int*)(sm + TOK_OFF);
    float* biasS = (float*)(sm + BIAS_OFF);
    const float* bias = e ? b1v : b0v;
    if (tid < BM) {
        int r = rowBase + tid;
        tokS[tid] = (r < cnt) ? g_idx[e * NTOK + r] : -1;
        biasS[tid] = bias[colBase + tid];
    }

    const float* Xbase = g_Xg + ((size_t)e * NTOK + rowBase) * D_DIM;
    const float* Wbase = &g_Wr[e][0] + colBase;

    // A: 512 float4/tile, 4 per thread; B: 512 float4/tile, 4 per thread
    int am[4], akc[4], bkr[4], bn4[4];
    uint32_t adst[4], bdst[4];
    #pragma unroll
    for (int q = 0; q < 4; q++) {
        int ia = q * THREADS + tid;
        am[q]  = ia >> 2;  akc[q] = ia & 3;
        bkr[q] = ia >> 5;  bn4[q] = ia & 31;
        adst[q] = smb + (uint32_t)(am[q] * APAD + akc[q] * 4) * 4;
        bdst[q] = smb + ASZ + (uint32_t)(bkr[q] * BPAD + bn4[q] * 4) * 4;
    }

    // prologue
    #pragma unroll
    for (int t = 0; t < NSTAGE - 1; t++) {
        #pragma unroll
        for (int q = 0; q < 4; q++) {
            cp16(adst[q] + t * STAGE, Xbase + (size_t)am[q] * D_DIM + t * BK + akc[q] * 4);
            cp16(bdst[q] + t * STAGE, Wbase + (size_t)(t * BK + bkr[q]) * OUT_DIM + bn4[q] * 4);
        }
        CP_COMMIT();
    }

    float acc[4][8][4];
    #pragma unroll
    for (int mt = 0; mt < 4; mt++)
        #pragma unroll
        for (int nt = 0; nt < 8; nt++)
            #pragma unroll
            for (int r = 0; r < 4; r++) acc[mt][nt][r] = 0.f;

    for (int i = 0; i < KITERS; i++) {
        CP_WAIT2();
        __syncthreads();

        const int t = i + NSTAGE - 1;
        if (t < KITERS) {
            const int fs = t & (NSTAGE - 1);
            #pragma unroll
            for (int q = 0; q < 4; q++) {
                cp16(adst[q] + fs * STAGE, Xbase + (size_t)am[q] * D_DIM + t * BK + akc[q] * 4);
                cp16(bdst[q] + fs * STAGE, Wbase + (size_t)(t * BK + bkr[q]) * OUT_DIM + bn4[q] * 4);
            }
            CP_COMMIT();
        }

        const int slot = i & (NSTAGE - 1);
        const float* As = (const float*)(sm + slot * STAGE);
        const float* Bs = (const float*)(sm + slot * STAGE + ASZ);

        #pragma unroll
        for (int ks = 0; ks < 2; ks++) {
            uint32_t af[4][4], bf[8][2];
            #pragma unroll
            for (int mt = 0; mt < 4; mt++) {
                const int m = wr * 64 + mt * 16;
                af[mt][0] = __float_as_uint(As[(m + g)     * APAD + ks * 8 + c]);
                af[mt][1] = __float_as_uint(As[(m + g + 8) * APAD + ks * 8 + c]);
                af[mt][2] = __float_as_uint(As[(m + g)     * APAD + ks * 8 + c + 4]);
                af[mt][3] = __float_as_uint(As[(m + g + 8) * APAD + ks * 8 + c + 4]);
            }
            #pragma unroll
            for (int nt = 0; nt < 8; nt++) {
                const int n = wc * 64 + nt * 8 + g;
                bf[nt][0] = __float_as_uint(Bs[(ks * 8 + c)     * BPAD + n]);
                bf[nt][1] = __float_as_uint(Bs[(ks * 8 + c + 4) * BPAD + n]);
            }
            #pragma unroll
            for (int mt = 0; mt < 4; mt++)
                #pragma unroll
                for (int nt = 0; nt < 8; nt++)
                    mma_tf32(acc[mt][nt], af[mt], bf[nt]);
        }
        __syncthreads();
    }

    // ---- epilogue ----
    const size_t pMine  = (size_t)e * PLANE;
    const size_t pOther = (size_t)(1 - e) * PLANE;

    #pragma unroll
    for (int mt = 0; mt < 4; mt++) {
        #pragma unroll
        for (int half = 0; half < 2; half++) {
            const int r = wr * 64 + mt * 16 + g + half * 8;
            const int tok = tokS[r];
            if (tok < 0) continue;
            float* po = out + pMine  + (size_t)tok * OUT_DIM + colBase;
            float* pz = out + pOther + (size_t)tok * OUT_DIM + colBase;
            #pragma unroll
            for (int nt = 0; nt < 8; nt++) {
                const int coll = wc * 64 + nt * 8 + 2 * c;
                const float v0 = acc[mt][nt][half * 2 + 0] + biasS[coll];
                const float v1 = acc[mt][nt][half * 2 + 1] + biasS[coll + 1];
                *(float2*)(po + coll) = make_float2(v0, v1);
                *(float2*)(pz + coll) = make_float2(0.f, 0.f);
            }
        }
    }
}

// ---------------- launch ----------------
extern "C" void kernel_launch(void* const* d_in, const int* in_sizes, int n_in,
                              void* d_out, int out_size)
{
    const float* X   = (const float*)d_in[0];
    const int*   tid = (const int*)  d_in[1];
    const float* W0  = (const float*)d_in[2];
    const float* b0  = (const float*)d_in[3];
    const float* W1  = (const float*)d_in[4];
    const float* b1  = (const float*)d_in[5];
    float* out = (float*)d_out;

    cudaFuncSetAttribute(moe_gemm_mma, cudaFuncAttributeMaxDynamicSharedMemorySize, SMEM_REQ);

    reset_counts_kernel<<<1, 32>>>();
    build_lists_kernel<<<(NTOK + 255) / 256, 256>>>(tid);
    round_w_kernel<<<(2 * D_DIM * OUT_DIM / 4 + 255) / 256, 256>>>(W0, W1);
    gather_x_kernel<<<(NMOD * NTOK) / 4, 256>>>(X);

    dim3 grid(OUT_DIM / BN, NTOK / BM, NMOD);   // 32 x 128 x 2
    moe_gemm_mma<<<grid, THREADS, SMEM_REQ>>>(b0, b1, out);
}

// round 5
// speedup vs baseline: 4.5530x; 1.2651x over previous
#include <cuda_runtime.h>
#include <cstdint>

// ---------------- problem constants ----------------
#define NTOK    16384
#define D_DIM   1024
#define OUT_DIM 4096
#define NMOD    2
#define PLANE   ((size_t)NTOK * OUT_DIM)

#define BM 128
#define BN 128
#define BK 16                      // 2 ktiles of 8 per iter
#define KITERS (D_DIM / BK)        // 64
#define NKT    (D_DIM / 8)         // 128 ktiles total
#define NRT    (NTOK / 16)         // 1024 row tiles per expert
#define NSTAGE 4
#define THREADS 128                // 4 warps, 64x64 warp tile

// smem: per stage A 8KB ([mt8][kt2][lane32][4]f) + B 8KB ([kt2][n128][c4][2]f)
#define ASZ   8192
#define BSZ   8192
#define STAGE (ASZ + BSZ)          // 16384
#define TOK_OFF  (NSTAGE * STAGE)  // 65536
#define BIAS_OFF (TOK_OFF + BM * 4)
#define SMEM_REQ (BIAS_OFF + BN * 4 + 128)

// ---------------- scratch ----------------
__device__ int   g_counts[NMOD];
__device__ int   g_idx[NMOD * NTOK];
// A packed: [e][rt][ktg][lane][4] ; float idx = ((e*NRT+rt)*NKT+ktg)*128 + lane*4
__device__ float g_Xg[(size_t)NMOD * NTOK * D_DIM];
// B packed: [e][ktg][n][c][2]    ; float idx = ((e*NKT+ktg)*OUT_DIM+n)*8 + c*2
__device__ float g_Wr[(size_t)NMOD * D_DIM * OUT_DIM];

// ---------------- helpers ----------------
__device__ __forceinline__ uint32_t smem_u32(const void* p) {
    uint32_t a;
    asm("{ .reg .u64 t; cvta.to.shared.u64 t, %1; cvt.u32.u64 %0, t; }" : "=r"(a) : "l"(p));
    return a;
}
__device__ __forceinline__ float rn_tf32(float x) {
    uint32_t r;
    asm("cvt.rna.tf32.f32 %0, %1;" : "=r"(r) : "f"(x));
    return __uint_as_float(r);
}
__device__ __forceinline__ void cp16(uint32_t dst, const void* src) {
    asm volatile("cp.async.cg.shared.global [%0], [%1], 16;" :: "r"(dst), "l"(src));
}
#define CP_COMMIT() asm volatile("cp.async.commit_group;" ::: "memory")
#define CP_WAIT2()  asm volatile("cp.async.wait_group 2;" ::: "memory")

__device__ __forceinline__ void mma_tf32(float* d, const uint32_t* a, const uint32_t* b) {
    asm volatile(
        "mma.sync.aligned.m16n8k8.row.col.f32.tf32.tf32.f32 "
        "{%0,%1,%2,%3}, {%4,%5,%6,%7}, {%8,%9}, {%0,%1,%2,%3};"
        : "+f"(d[0]), "+f"(d[1]), "+f"(d[2]), "+f"(d[3])
        : "r"(a[0]), "r"(a[1]), "r"(a[2]), "r"(a[3]), "r"(b[0]), "r"(b[1]));
}

// ---------------- routing ----------------
__global__ void reset_counts_kernel() {
    if (threadIdx.x < NMOD) g_counts[threadIdx.x] = 0;
}
__global__ void build_lists_kernel(const int* __restrict__ type_ids) {
    int i = blockIdx.x * blockDim.x + threadIdx.x;
    if (i < NTOK) {
        int t = type_ids[i];
        int p = atomicAdd(&g_counts[t], 1);
        g_idx[t * NTOK + p] = i;
    }
}

// ---------------- W prep: round + pack fragment pairs ----------------
// element (e, ktg, c, n): float2 { W[ktg*8+c][n], W[ktg*8+c+4][n] }
__global__ void pack_w_kernel(const float* __restrict__ W0, const float* __restrict__ W1) {
    unsigned i = blockIdx.x * blockDim.x + threadIdx.x;   // 2*128*4*4096 = 4M
    int n   = i & (OUT_DIM - 1);
    int c   = (i >> 12) & 3;
    int ktg = (i >> 14) & (NKT - 1);
    int e   = i >> 21;
    const float* W = e ? W1 : W0;
    float lo = rn_tf32(W[(size_t)(ktg * 8 + c)     * OUT_DIM + n]);
    float hi = rn_tf32(W[(size_t)(ktg * 8 + c + 4) * OUT_DIM + n]);
    float2* dst = (float2*)g_Wr + (((size_t)(e * NKT + ktg) * OUT_DIM + n) * 4 + c);
    *dst = make_float2(lo, hi);
}

// ---------------- X prep: gather + round + pack fragments ----------------
// one warp per (e, rt); lane(g=lane>>2, c=lane&3) produces float4 per ktile
__global__ void gather_x_kernel(const float* __restrict__ X) {
    int w = (blockIdx.x * blockDim.x + threadIdx.x) >> 5;   // 0..2047
    int lane = threadIdx.x & 31;
    int e  = w >> 10;
    int rt = w & (NRT - 1);
    int cnt = g_counts[e];
    if (rt * 16 >= cnt) return;

    int r = rt * 16 + lane;
    int tokv = (lane < 16 && r < cnt) ? g_idx[e * NTOK + r] : -1;
    int g = lane >> 2, c = lane & 3;
    int t0 = __shfl_sync(0xFFFFFFFFu, tokv, g);
    int t1 = __shfl_sync(0xFFFFFFFFu, tokv, g + 8);
    const float* x0 = X + (size_t)(t0 < 0 ? 0 : t0) * D_DIM;
    const float* x1 = X + (size_t)(t1 < 0 ? 0 : t1) * D_DIM;
    float m0 = (t0 < 0) ? 0.f : 1.f;
    float m1 = (t1 < 0) ? 0.f : 1.f;

    float4* dst = (float4*)g_Xg + ((size_t)(e * NRT + rt) * NKT) * 32 + lane;
    #pragma unroll 4
    for (int kt = 0; kt < NKT; kt++) {
        int k = kt * 8 + c;
        float4 v;
        v.x = rn_tf32(x0[k]     * m0);
        v.y = rn_tf32(x1[k]     * m1);
        v.z = rn_tf32(x0[k + 4] * m0);
        v.w = rn_tf32(x1[k + 4] * m1);
        dst[kt * 32] = v;
    }
}

// ---------------- tf32 mma.sync GEMM, fragment-packed operands ----------------
__global__ __launch_bounds__(THREADS, 2)
void moe_gemm_mma(const float* __restrict__ b0v, const float* __restrict__ b1v,
                  float* __restrict__ out)
{
    const int e = blockIdx.z;
    const int cnt = g_counts[e];
    const int rowBase = blockIdx.y * BM;
    if (rowBase >= cnt) return;
    const int colBase = blockIdx.x * BN;

    extern __shared__ char sm[];
    const uint32_t smb = smem_u32(sm);

    const int tid = threadIdx.x;
    const int wid = tid >> 5;
    const int lane = tid & 31;
    const int g = lane >> 2;
    const int c = lane & 3;
    const int wr = wid & 1;
    const int wc = wid >> 1;

    int*   tokS  = (int*)(sm + TOK_OFF);
    float* biasS = (float*)(sm + BIAS_OFF);
    const float* bias = e ? b1v : b0v;
    {
        int r = rowBase + tid;
        tokS[tid] = (r < cnt) ? g_idx[e * NTOK + r] : -1;
        biasS[tid] = bias[colBase + tid];
    }

    // ---- cp.async source/dest mapping (4 float4 per thread for A and B) ----
    // A: qa = q*128+tid; lane_a=qa&31; kt_a=(qa>>5)&1; mt_a=qa>>6
    // B: qb = q*128+tid; kt_b=qb>>8; nloc=(qb&255)>>1; ch=qb&1
    const float* Ab = g_Xg + ((size_t)(e * NRT + blockIdx.y * 8) * NKT) * 128;
    const float* Bb = g_Wr + ((size_t)e * NKT * OUT_DIM + colBase) * 8;

    const float* asrc[4]; const float* bsrc[4];
    uint32_t adst[4], bdst[4];
    int aktg[4], bktg[4];
    #pragma unroll
    for (int q = 0; q < 4; q++) {
        int qa = q * THREADS + tid;
        int la = qa & 31, kta = (qa >> 5) & 1, mta = qa >> 6;
        aktg[q] = kta;
        asrc[q] = Ab + (size_t)mta * NKT * 128 + la * 4;
        adst[q] = smb + qa * 16;
        int qb = qa;
        int ktb = qb >> 8, nloc = (qb & 255) >> 1, ch = qb & 1;
        bktg[q] = ktb;
        bsrc[q] = Bb + (size_t)nloc * 8 + ch * 4;
        bdst[q] = smb + ASZ + qb * 16;
    }

    // prologue: stages 0..2
    #pragma unroll
    for (int t = 0; t < NSTAGE - 1; t++) {
        #pragma unroll
        for (int q = 0; q < 4; q++) {
            cp16(adst[q] + t * STAGE, asrc[q] + (size_t)(2 * t + aktg[q]) * 128);
            cp16(bdst[q] + t * STAGE, bsrc[q] + (size_t)(2 * t + bktg[q]) * OUT_DIM * 8);
        }
        CP_COMMIT();
    }

    float acc[4][8][4];
    #pragma unroll
    for (int mt = 0; mt < 4; mt++)
        #pragma unroll
        for (int nt = 0; nt < 8; nt++)
            #pragma unroll
            for (int r2 = 0; r2 < 4; r2++) acc[mt][nt][r2] = 0.f;

    // in-loop fragment addresses
    // af[mt]: As + ((wr*4+mt)*2 + kt)*512 + lane*16
    // bf[nt]: Bs + ((kt*128 + wc*64 + nt*8 + g)*4 + c)*8
    const uint32_t afb = smb + (uint32_t)(wr * 4) * 1024 + lane * 16;
    const uint32_t bfb = smb + ASZ + ((uint32_t)(wc * 64 + g) * 4 + c) * 8;

    for (int i = 0; i < KITERS; i++) {
        CP_WAIT2();
        __syncthreads();

        const int t = i + NSTAGE - 1;
        if (t < KITERS) {
            const int fs = t & (NSTAGE - 1);
            #pragma unroll
            for (int q = 0; q < 4; q++) {
                cp16(adst[q] + fs * STAGE, asrc[q] + (size_t)(2 * t + aktg[q]) * 128);
                cp16(bdst[q] + fs * STAGE, bsrc[q] + (size_t)(2 * t + bktg[q]) * OUT_DIM * 8);
            }
            CP_COMMIT();
        }

        const uint32_t stg = (i & (NSTAGE - 1)) * STAGE;
        #pragma unroll
        for (int kt = 0; kt < 2; kt++) {
            uint32_t af[4][4], bf[8][2];
            #pragma unroll
            for (int mt = 0; mt < 4; mt++) {
                asm volatile("ld.shared.v4.b32 {%0,%1,%2,%3}, [%4];"
                    : "=r"(af[mt][0]), "=r"(af[mt][1]), "=r"(af[mt][2]), "=r"(af[mt][3])
                    : "r"(afb + stg + (uint32_t)(mt * 2 + kt) * 512));
            }
            #pragma unroll
            for (int nt = 0; nt < 8; nt++) {
                asm volatile("ld.shared.v2.b32 {%0,%1}, [%2];"
                    : "=r"(bf[nt][0]), "=r"(bf[nt][1])
                    : "r"(bfb + stg + (uint32_t)(kt * 128 + nt * 8) * 32));
            }
            #pragma unroll
            for (int mt = 0; mt < 4; mt++)
                #pragma unroll
                for (int nt = 0; nt < 8; nt++)
                    mma_tf32(acc[mt][nt], af[mt], bf[nt]);
        }
        __syncthreads();
    }

    // ---- epilogue ----
    const size_t pMine  = (size_t)e * PLANE;
    const size_t pOther = (size_t)(1 - e) * PLANE;

    #pragma unroll
    for (int mt = 0; mt < 4; mt++) {
        #pragma unroll
        for (int half = 0; half < 2; half++) {
            const int r = wr * 64 + mt * 16 + g + half * 8;
            const int tok = tokS[r];
            if (tok < 0) continue;
            float* po = out + pMine  + (size_t)tok * OUT_DIM + colBase;
            float* pz = out + pOther + (size_t)tok * OUT_DIM + colBase;
            #pragma unroll
            for (int nt = 0; nt < 8; nt++) {
                const int coll = wc * 64 + nt * 8 + 2 * c;
                const float v0 = acc[mt][nt][half * 2 + 0] + biasS[coll];
                const float v1 = acc[mt][nt][half * 2 + 1] + biasS[coll + 1];
                *(float2*)(po + coll) = make_float2(v0, v1);
                *(float2*)(pz + coll) = make_float2(0.f, 0.f);
            }
        }
    }
}

// ---------------- launch ----------------
extern "C" void kernel_launch(void* const* d_in, const int* in_sizes, int n_in,
                              void* d_out, int out_size)
{
    const float* X   = (const float*)d_in[0];
    const int*   tid = (const int*)  d_in[1];
    const float* W0  = (const float*)d_in[2];
    const float* b0  = (const float*)d_in[3];
    const float* W1  = (const float*)d_in[4];
    const float* b1  = (const float*)d_in[5];
    float* out = (float*)d_out;

    cudaFuncSetAttribute(moe_gemm_mma, cudaFuncAttributeMaxDynamicSharedMemorySize, SMEM_REQ);

    reset_counts_kernel<<<1, 32>>>();
    build_lists_kernel<<<(NTOK + 255) / 256, 256>>>(tid);
    pack_w_kernel<<<(NMOD * NKT * 4 * OUT_DIM) / 256, 256>>>(W0, W1);
    gather_x_kernel<<<(NMOD * NRT * 32) / 256, 256>>>(X);

    dim3 grid(OUT_DIM / BN, NTOK / BM, NMOD);   // 32 x 128 x 2
    moe_gemm_mma<<<grid, THREADS, SMEM_REQ>>>(b0, b1, out);
}